// round 5
// baseline (speedup 1.0000x reference)
#include <cuda_runtime.h>

#define CUT  14
#define DIM  2744          // 14^3
#define SECT 1834          // sum over sectors of c(s)^2
#define NT   448           // evolve threads per CTA

// ---------------- persistent device scratch (no allocs allowed) ----------------
__device__ float2 g_bs[24][SECT];        // 24 beamsplitter gates, sector-packed
__device__ float2 g_sng[24][CUT*CUT];    // 24 combined single-mode gates
__device__ float  g_dvec[2][1024][3][CUT]; // initial displacement vectors (real)

// ---------------- packed f32x2 helpers ----------------
__device__ __forceinline__ unsigned long long pk2(float lo, float hi) {
  unsigned long long r;
  asm("mov.b64 %0, {%1, %2};" : "=l"(r) : "f"(lo), "f"(hi));
  return r;
}
__device__ __forceinline__ void upk2(unsigned long long v, float& lo, float& hi) {
  asm("mov.b64 {%0, %1}, %2;" : "=f"(lo), "=f"(hi) : "l"(v));
}
__device__ __forceinline__ unsigned long long f2fma(unsigned long long a,
                                                    unsigned long long b,
                                                    unsigned long long c) {
  unsigned long long d;
  asm("fma.rn.f32x2 %0, %1, %2, %3;" : "=l"(d) : "l"(a), "l"(b), "l"(c));
  return d;
}

// ================= gate precompute: fp32 expm (s=8, terms=12, banded Taylor) =================
// tasks [0,648): BS gate sector blocks (24 gates x 27 sectors)
// tasks [648,672): single-mode combined gates (12 squeeze->M1, 12 disp->M2)
__global__ void __launch_bounds__(196) gates_kernel(
    const float* __restrict__ th1, const float* __restrict__ ph1,
    const float* __restrict__ vph1, const float* __restrict__ rr,
    const float* __restrict__ phr, const float* __restrict__ th2,
    const float* __restrict__ ph2, const float* __restrict__ vph2,
    const float* __restrict__ aa, const float* __restrict__ pha,
    const float* __restrict__ kk)
{
  __shared__ float2 Bm[196], Ta[196], Tb[196], Ot[196];
  const int tid = threadIdx.x;
  const int i = tid / CUT, j = tid % CUT;
  const int task = blockIdx.x;

  int c = CUT, s = 0, pm = 0, gid = -1;
  double2 h = make_double2(0.0, 0.0);

  if (task < 648) {
    gid = task / 27; s = task % 27;
    pm = (s < CUT) ? 0 : s - (CUT-1);
    c  = (s < CUT) ? s + 1 : 2*CUT - 1 - s;
    int circ = gid / 12, rem = gid % 12;
    int l = rem / 6, w = (rem / 3) % 2, p = rem % 3;
    int pi = (circ*2 + l)*3 + p;
    double th = (double)((w ? th2 : th1)[pi]);
    double ph = (double)((w ? ph2 : ph1)[pi]);
    if (i < c && j < c) {
      int P = pm + i, Q = s - P;
      if (j == i - 1) {            // theta*e^{i phi} * sqrt(P*(Q+1))
        double mag = th * sqrt((double)P * (double)(Q + 1));
        h.x = mag * cos(ph); h.y = mag * sin(ph);
      } else if (j == i + 1) {     // -theta*e^{-i phi} * sqrt((P+1)*Q)
        double mag = th * sqrt((double)(P + 1) * (double)Q);
        h.x = -mag * cos(ph); h.y = mag * sin(ph);
      }
    }
  } else {
    int u = task - 648;
    int circ = u / 12, rem = u % 12;
    int l = rem / 6, w = (rem / 3) % 2, m = rem % 3;
    int pi = (circ*2 + l)*3 + m;
    if (w == 0) {  // squeeze
      double rv = (double)rr[pi], pv = (double)phr[pi];
      double zr = rv*cos(pv), zi = rv*sin(pv);
      if (j == i + 2) {
        double mag = 0.5*sqrt((double)(i+1)*(double)(i+2));
        h.x = mag*zr; h.y = -mag*zi;
      } else if (i == j + 2) {
        double mag = 0.5*sqrt((double)(j+1)*(double)(j+2));
        h.x = -mag*zr; h.y = -mag*zi;
      }
    } else {       // disp
      double av = (double)aa[pi], pv = (double)pha[pi];
      double ar = av*cos(pv), ai = av*sin(pv);
      if (i == j + 1) {
        double mag = sqrt((double)(j+1));
        h.x = mag*ar; h.y = mag*ai;
      } else if (j == i + 1) {
        double mag = sqrt((double)(i+1));
        h.x = -mag*ar; h.y = mag*ai;
      }
    }
  }

  const bool act = (i < c && j < c);
  const double sc = 1.0/256.0;   // 2^-8
  Bm[tid] = make_float2((float)(h.x*sc), (float)(h.y*sc));
  float idv = (act && i == j) ? 1.0f : 0.0f;
  Ta[tid] = make_float2(idv, 0.0f);
  Ot[tid] = make_float2(idv, 0.0f);
  __syncthreads();

  // Taylor phase: B is at most pentadiagonal -> only t in [j-2, j+2] contributes
  const int t_lo = (j >= 2) ? j - 2 : 0;
  float2* term = Ta; float2* nxt = Tb;
  for (int k = 1; k <= 12; k++) {
    float2 acc = make_float2(0.f, 0.f);
    if (act) {
      int t_hi = (j + 2 < c - 1) ? j + 2 : c - 1;
      for (int t = t_lo; t <= t_hi; t++) {
        float2 xv = term[i*CUT + t], yv = Bm[t*CUT + j];
        acc.x += xv.x*yv.x - xv.y*yv.y;
        acc.y += xv.x*yv.y + xv.y*yv.x;
      }
      float inv = 1.0f/(float)k;
      acc.x *= inv; acc.y *= inv;
      nxt[i*CUT + j] = acc;
      Ot[i*CUT + j].x += acc.x;
      Ot[i*CUT + j].y += acc.y;
    }
    float2* z = term; term = nxt; nxt = z;
    __syncthreads();
  }
  for (int q = 0; q < 8; q++) {   // 8 squarings (2^8 scaling)
    float2 acc = make_float2(0.f, 0.f);
    if (act) {
      for (int t = 0; t < c; t++) {
        float2 xv = Ot[i*CUT + t], yv = Ot[t*CUT + j];
        acc.x += xv.x*yv.x - xv.y*yv.y;
        acc.y += xv.x*yv.y + xv.y*yv.x;
      }
    }
    __syncthreads();
    if (act) Ot[i*CUT + j] = acc;
    __syncthreads();
  }

  if (task < 648) {
    if (act) {
      int off = (s < CUT) ? s*(s+1)*(2*s+1)/6
                          : SECT - ((27-s)*(28-s)*(55-2*s))/6;
      g_bs[gid][off + i*c + j] = Ot[tid];
    }
  } else {
    int u = task - 648;
    int circ = u / 12, rem = u % 12;
    int l = rem / 6, w = (rem / 3) % 2, m = rem % 3;
    int pi = (circ*2 + l)*3 + m;
    double phase;
    if (w == 0) phase = (double)vph1[pi] * (double)j;                        // M1 = S * R(vph1)
    else        phase = (double)vph2[pi] * (double)j + (double)kk[pi]*(double)(i*i); // M2 = K*D*R(vph2)
    float cr = (float)cos(phase), ci = (float)sin(phase);
    float2 sv = Ot[tid];
    g_sng[u][tid] = make_float2(sv.x*cr - sv.y*ci, sv.x*ci + sv.y*cr);
  }
}

// ============ initial displacement vectors: coherent-state closed form ============
// exp(x(A^dag - A))|0> = e^{-x^2/2} sum_n x^n/sqrt(n!) |n>   (exact)
__global__ void __launch_bounds__(256) dvec_kernel(const float* __restrict__ x)
{
  int tid = blockIdx.x*blockDim.x + threadIdx.x;
  if (tid >= 1024*6) return;
  int b = tid / 6, colx = tid % 6, circ = colx / 3, m = colx % 3;
  double xv = (double)x[tid];
  double c = exp(-0.5 * xv * xv);
  #pragma unroll
  for (int n = 0; n < CUT; n++) {
    g_dvec[circ][b][m][n] = (float)c;
    c *= xv * rsqrt((double)(n + 1));
  }
}

// ================= main evolution: one CTA per (batch, circuit) =================
__global__ void __launch_bounds__(NT, 3) evolve_kernel(float* __restrict__ out)
{
  __shared__ unsigned long long spl[DIM];   // state, (re,im) packed
  __shared__ unsigned long long sgxx[SECT]; // gate.(x,x) duplicated pairs
  __shared__ unsigned long long sgyy[SECT]; // gate.(y,y) duplicated pairs
  __shared__ float  sd[3*CUT];
  __shared__ float  sred[NT/32];

  float2* sp = (float2*)spl;
  const int tid = threadIdx.x;
  const int b = blockIdx.x, circ = blockIdx.y;

  if (tid < 3*CUT) sd[tid] = g_dvec[circ][b][tid/CUT][tid%CUT];
  __syncthreads();
  for (int idx = tid; idx < DIM; idx += NT) {
    int i0 = idx / 196, j0 = (idx / CUT) % CUT, k0 = idx % CUT;
    spl[idx] = pk2(sd[i0]*sd[CUT + j0]*sd[2*CUT + k0], 0.0f);
  }

  // ---- BS job decode: 392 jobs = (sector cell) x (fiber half of 7) ----
  int s = 0, csz = 1, pm = 0, gbase = 0, row = 0, col = 0, r0 = 0;
  const bool bs_act = (tid < 392);
  if (bs_act) {
    int jj = tid, cum = 0, ss = 0;
    for (ss = 0; ss < 27; ss++) {
      int cc = (ss < CUT) ? ss + 1 : 27 - ss;
      if (jj < cum + 2*cc) break;
      cum += 2*cc;
    }
    s   = ss;
    csz = (s < CUT) ? s + 1 : 27 - s;
    pm  = (s < CUT) ? 0 : s - 13;
    int q = jj - cum;
    int half = q / csz;
    int idxs = q % csz;
    r0  = half * 7;
    row = pm + idxs; col = s - row;
    int off = (s < CUT) ? s*(s+1)*(2*s+1)/6 : SECT - ((27-s)*(28-s)*(55-2*s))/6;
    gbase = off + idxs*csz;
  }
  const int in01 = (pm*13 + s)*CUT;         // mode01 input base (u stride 182)
  const int ob01 = (row*CUT + col)*CUT;     // mode01 output base
  const int in12 = pm*13 + s;               // mode12 input base (u stride 13)
  const int ob12 = row*CUT + col;           // mode12 output cell (i stride 196)

  // ---- single-mode job decode: 392 jobs = (output row a) x (fiber group of 7) ----
  const int sm_a   = tid % CUT;             // output row
  const int sm_grp = tid / CUT;             // fiber group (0..27 valid)
  const bool sm_act = (tid < 392);
  __syncthreads();

  const int m1s[3] = {0, 1, 0};   // PAIRS = [(0,1),(1,2),(0,1)]
  for (int l = 0; l < 2; l++) {
    for (int half_ = 0; half_ < 2; half_++) {
      // ---- 3 beamsplitter gates ----
      for (int p = 0; p < 3; p++) {
        const float4* gm4 = (const float4*)g_bs[(circ*2 + l)*6 + half_*3 + p];
        for (int ii = tid; ii < SECT/2; ii += NT) {   // 128-bit staging loads
          float4 w2 = gm4[ii];
          sgxx[2*ii]   = pk2(w2.x, w2.x);
          sgyy[2*ii]   = pk2(w2.y, w2.y);
          sgxx[2*ii+1] = pk2(w2.z, w2.z);
          sgyy[2*ii+1] = pk2(w2.w, w2.w);
        }
        __syncthreads();
        unsigned long long accA[7], accB[7];
        if (bs_act) {
          #pragma unroll
          for (int r = 0; r < 7; r++) { accA[r] = 0ull; accB[r] = 0ull; }
          if (m1s[p] == 0) {          // contract axes (0,1); fiber axis 2 (stride 1)
            const unsigned long long* fbase = spl + in01 + r0;
            for (int u = 0; u < csz; u++) {
              unsigned long long wxx = sgxx[gbase + u], wyy = sgyy[gbase + u];
              const unsigned long long* f = fbase + u*182;
              #pragma unroll
              for (int r = 0; r < 7; r++) {
                unsigned long long v = f[r];
                accA[r] = f2fma(wxx, v, accA[r]);
                accB[r] = f2fma(wyy, v, accB[r]);
              }
            }
          } else {                    // contract axes (1,2); fiber axis 0 (stride 196)
            const unsigned long long* fbase = spl + in12 + r0*196;
            for (int u = 0; u < csz; u++) {
              unsigned long long wxx = sgxx[gbase + u], wyy = sgyy[gbase + u];
              const unsigned long long* f = fbase + u*13;
              #pragma unroll
              for (int r = 0; r < 7; r++) {
                unsigned long long v = f[r*196];
                accA[r] = f2fma(wxx, v, accA[r]);
                accB[r] = f2fma(wyy, v, accB[r]);
              }
            }
          }
        }
        __syncthreads();
        if (bs_act) {
          #pragma unroll
          for (int r = 0; r < 7; r++) {
            float ax, ay, bx, by;
            upk2(accA[r], ax, ay); upk2(accB[r], bx, by);
            unsigned long long res = pk2(ax - by, ay + bx);
            if (m1s[p] == 0) spl[ob01 + r0 + r] = res;
            else             spl[(r0 + r)*196 + ob12] = res;
          }
        }
        __syncthreads();
      }
      // ---- 3 combined single-mode gates (direct [a][t] layout, 392-thread staging) ----
      for (int m = 0; m < 3; m++) {
        const float2* gm = g_sng[(circ*2 + l)*6 + half_*3 + m];
        if (tid < 392) {
          int e = tid % 196;                 // e = a*CUT + t
          float2 w = gm[e];
          if (tid < 196) sgxx[e] = pk2(w.x, w.x);
          else           sgyy[e] = pk2(w.y, w.y);
        }
        __syncthreads();
        unsigned long long accA[7], accB[7];
        int start = 0, ts = 1, fs = 1;
        if (sm_act) {
          if (m == 0)      { start = sm_grp*7;                                ts = 196; fs = 1;  }
          else if (m == 1) { start = (sm_grp >> 1)*196 + (sm_grp & 1)*7;      ts = CUT; fs = 1;  }
          else             { start = sm_grp*7*CUT;                            ts = 1;   fs = CUT;}
          #pragma unroll
          for (int q = 0; q < 7; q++) { accA[q] = 0ull; accB[q] = 0ull; }
          for (int t = 0; t < CUT; t++) {
            unsigned long long gxx = sgxx[sm_a*CUT + t], gyy = sgyy[sm_a*CUT + t];
            const unsigned long long* f = spl + start + t*ts;
            #pragma unroll
            for (int q = 0; q < 7; q++) {
              unsigned long long v = f[q*fs];
              accA[q] = f2fma(gxx, v, accA[q]);
              accB[q] = f2fma(gyy, v, accB[q]);
            }
          }
        }
        __syncthreads();
        if (sm_act) {
          unsigned long long* o = spl + start + sm_a*ts;
          #pragma unroll
          for (int q = 0; q < 7; q++) {
            float ax, ay, bx, by;
            upk2(accA[q], ax, ay); upk2(accB[q], bx, by);
            o[q*fs] = pk2(ax - by, ay + bx);
          }
        }
        __syncthreads();
      }
    }
  }

  // ---- expectations <psi| (A + A^dag)_m |psi> ----
  for (int m = 0; m < 3; m++) {
    float local = 0.f;
    const int st = (m == 0) ? 196 : (m == 1) ? CUT : 1;
    for (int idx = tid; idx < DIM; idx += NT) {
      int n = (m == 0) ? idx/196 : (m == 1) ? (idx/CUT)%CUT : idx%CUT;
      if (n < CUT-1) {
        float2 a2 = sp[idx], b2 = sp[idx + st];
        local += sqrtf((float)(n+1)) * (a2.x*b2.x + a2.y*b2.y);
      }
    }
    #pragma unroll
    for (int o = 16; o > 0; o >>= 1) local += __shfl_down_sync(0xffffffffu, local, o);
    if ((tid & 31) == 0) sred[tid >> 5] = local;
    __syncthreads();
    if (tid == 0) {
      float tot = 0.f;
      #pragma unroll
      for (int w2 = 0; w2 < NT/32; w2++) tot += sred[w2];
      out[b*6 + circ*3 + m] = 2.f * tot;
    }
    __syncthreads();
  }
}

// ================================ launch ================================
extern "C" void kernel_launch(void* const* d_in, const int* in_sizes, int n_in,
                              void* d_out, int out_size)
{
  (void)in_sizes; (void)n_in; (void)out_size;
  const float* x    = (const float*)d_in[0];
  const float* th1  = (const float*)d_in[1];
  const float* ph1  = (const float*)d_in[2];
  const float* vph1 = (const float*)d_in[3];
  const float* rr   = (const float*)d_in[4];
  const float* phr  = (const float*)d_in[5];
  const float* th2  = (const float*)d_in[6];
  const float* ph2  = (const float*)d_in[7];
  const float* vph2 = (const float*)d_in[8];
  const float* aa   = (const float*)d_in[9];
  const float* pha  = (const float*)d_in[10];
  const float* kk   = (const float*)d_in[11];

  gates_kernel<<<672, 196>>>(th1, ph1, vph1, rr, phr, th2, ph2, vph2, aa, pha, kk);
  dvec_kernel<<<24, 256>>>(x);
  dim3 grid(1024, 2);
  evolve_kernel<<<grid, NT>>>((float*)d_out);
}

// round 6
// speedup vs baseline: 2.3763x; 2.3763x over previous
#include <cuda_runtime.h>

#define CUT  14
#define DIM  2744          // 14^3
#define SECT 1834          // sum over sectors of c(s)^2
#define NT   448           // evolve threads per CTA

// ---------------- persistent device scratch (no allocs allowed) ----------------
__device__ float2 g_bs[24][SECT];        // 24 beamsplitter gates, sector-packed
__device__ float2 g_sng[24][CUT*CUT];    // 24 combined single-mode gates
__device__ float  g_dvec[2][1024][3][CUT]; // initial displacement vectors (real)

// ---------------- packed f32x2 helpers ----------------
__device__ __forceinline__ unsigned long long pk2(float lo, float hi) {
  unsigned long long r;
  asm("mov.b64 %0, {%1, %2};" : "=l"(r) : "f"(lo), "f"(hi));
  return r;
}
__device__ __forceinline__ void upk2(unsigned long long v, float& lo, float& hi) {
  asm("mov.b64 {%0, %1}, %2;" : "=f"(lo), "=f"(hi) : "l"(v));
}
__device__ __forceinline__ unsigned long long f2fma(unsigned long long a,
                                                    unsigned long long b,
                                                    unsigned long long c) {
  unsigned long long d;
  asm("fma.rn.f32x2 %0, %1, %2, %3;" : "=l"(d) : "l"(a), "l"(b), "l"(c));
  return d;
}

// ================= gate precompute: fp32 expm (s=8, terms=12, banded Taylor) =================
__global__ void __launch_bounds__(196) gates_kernel(
    const float* __restrict__ th1, const float* __restrict__ ph1,
    const float* __restrict__ vph1, const float* __restrict__ rr,
    const float* __restrict__ phr, const float* __restrict__ th2,
    const float* __restrict__ ph2, const float* __restrict__ vph2,
    const float* __restrict__ aa, const float* __restrict__ pha,
    const float* __restrict__ kk)
{
  __shared__ float2 Bm[196], Ta[196], Tb[196], Ot[196];
  const int tid = threadIdx.x;
  const int i = tid / CUT, j = tid % CUT;
  const int task = blockIdx.x;

  int c = CUT, s = 0, pm = 0, gid = -1;
  double2 h = make_double2(0.0, 0.0);

  if (task < 648) {
    gid = task / 27; s = task % 27;
    pm = (s < CUT) ? 0 : s - (CUT-1);
    c  = (s < CUT) ? s + 1 : 2*CUT - 1 - s;
    int circ = gid / 12, rem = gid % 12;
    int l = rem / 6, w = (rem / 3) % 2, p = rem % 3;
    int pi = (circ*2 + l)*3 + p;
    double th = (double)((w ? th2 : th1)[pi]);
    double ph = (double)((w ? ph2 : ph1)[pi]);
    if (i < c && j < c) {
      int P = pm + i, Q = s - P;
      if (j == i - 1) {            // theta*e^{i phi} * sqrt(P*(Q+1))
        double mag = th * sqrt((double)P * (double)(Q + 1));
        h.x = mag * cos(ph); h.y = mag * sin(ph);
      } else if (j == i + 1) {     // -theta*e^{-i phi} * sqrt((P+1)*Q)
        double mag = th * sqrt((double)(P + 1) * (double)Q);
        h.x = -mag * cos(ph); h.y = mag * sin(ph);
      }
    }
  } else {
    int u = task - 648;
    int circ = u / 12, rem = u % 12;
    int l = rem / 6, w = (rem / 3) % 2, m = rem % 3;
    int pi = (circ*2 + l)*3 + m;
    if (w == 0) {  // squeeze
      double rv = (double)rr[pi], pv = (double)phr[pi];
      double zr = rv*cos(pv), zi = rv*sin(pv);
      if (j == i + 2) {
        double mag = 0.5*sqrt((double)(i+1)*(double)(i+2));
        h.x = mag*zr; h.y = -mag*zi;
      } else if (i == j + 2) {
        double mag = 0.5*sqrt((double)(j+1)*(double)(j+2));
        h.x = -mag*zr; h.y = -mag*zi;
      }
    } else {       // disp
      double av = (double)aa[pi], pv = (double)pha[pi];
      double ar = av*cos(pv), ai = av*sin(pv);
      if (i == j + 1) {
        double mag = sqrt((double)(j+1));
        h.x = mag*ar; h.y = mag*ai;
      } else if (j == i + 1) {
        double mag = sqrt((double)(i+1));
        h.x = -mag*ar; h.y = mag*ai;
      }
    }
  }

  const bool act = (i < c && j < c);
  const double sc = 1.0/256.0;   // 2^-8
  Bm[tid] = make_float2((float)(h.x*sc), (float)(h.y*sc));
  float idv = (act && i == j) ? 1.0f : 0.0f;
  Ta[tid] = make_float2(idv, 0.0f);
  Ot[tid] = make_float2(idv, 0.0f);
  __syncthreads();

  const int t_lo = (j >= 2) ? j - 2 : 0;
  float2* term = Ta; float2* nxt = Tb;
  for (int k = 1; k <= 12; k++) {
    float2 acc = make_float2(0.f, 0.f);
    if (act) {
      int t_hi = (j + 2 < c - 1) ? j + 2 : c - 1;
      for (int t = t_lo; t <= t_hi; t++) {
        float2 xv = term[i*CUT + t], yv = Bm[t*CUT + j];
        acc.x += xv.x*yv.x - xv.y*yv.y;
        acc.y += xv.x*yv.y + xv.y*yv.x;
      }
      float inv = 1.0f/(float)k;
      acc.x *= inv; acc.y *= inv;
      nxt[i*CUT + j] = acc;
      Ot[i*CUT + j].x += acc.x;
      Ot[i*CUT + j].y += acc.y;
    }
    float2* z = term; term = nxt; nxt = z;
    __syncthreads();
  }
  for (int q = 0; q < 8; q++) {   // 8 squarings (2^8 scaling)
    float2 acc = make_float2(0.f, 0.f);
    if (act) {
      for (int t = 0; t < c; t++) {
        float2 xv = Ot[i*CUT + t], yv = Ot[t*CUT + j];
        acc.x += xv.x*yv.x - xv.y*yv.y;
        acc.y += xv.x*yv.y + xv.y*yv.x;
      }
    }
    __syncthreads();
    if (act) Ot[i*CUT + j] = acc;
    __syncthreads();
  }

  if (task < 648) {
    if (act) {
      int off = (s < CUT) ? s*(s+1)*(2*s+1)/6
                          : SECT - ((27-s)*(28-s)*(55-2*s))/6;
      g_bs[gid][off + i*c + j] = Ot[tid];
    }
  } else {
    int u = task - 648;
    int circ = u / 12, rem = u % 12;
    int l = rem / 6, w = (rem / 3) % 2, m = rem % 3;
    int pi = (circ*2 + l)*3 + m;
    double phase;
    if (w == 0) phase = (double)vph1[pi] * (double)j;                        // M1 = S * R(vph1)
    else        phase = (double)vph2[pi] * (double)j + (double)kk[pi]*(double)(i*i); // M2 = K*D*R(vph2)
    float cr = (float)cos(phase), ci = (float)sin(phase);
    float2 sv = Ot[tid];
    g_sng[u][tid] = make_float2(sv.x*cr - sv.y*ci, sv.x*ci + sv.y*cr);
  }
}

// ============ initial displacement vectors: coherent-state closed form ============
__global__ void __launch_bounds__(256) dvec_kernel(const float* __restrict__ x)
{
  int tid = blockIdx.x*blockDim.x + threadIdx.x;
  if (tid >= 1024*6) return;
  int b = tid / 6, colx = tid % 6, circ = colx / 3, m = colx % 3;
  double xv = (double)x[tid];
  double c = exp(-0.5 * xv * xv);
  #pragma unroll
  for (int n = 0; n < CUT; n++) {
    g_dvec[circ][b][m][n] = (float)c;
    c *= xv * rsqrt((double)(n + 1));
  }
}

// ================= main evolution: one CTA per (batch, circuit) =================
__global__ void __launch_bounds__(NT, 2) evolve_kernel(float* __restrict__ out)
{
  __shared__ unsigned long long spl[DIM];   // state, (re,im) packed
  __shared__ unsigned long long sgxx[SECT]; // gate.(x,x) duplicated pairs
  __shared__ unsigned long long sgyy[SECT]; // gate.(y,y) duplicated pairs
  __shared__ float  sd[3*CUT];
  __shared__ float  sred[3][NT/32];

  float2* sp = (float2*)spl;
  const int tid = threadIdx.x;
  const int b = blockIdx.x, circ = blockIdx.y;

  if (tid < 3*CUT) sd[tid] = g_dvec[circ][b][tid/CUT][tid%CUT];
  __syncthreads();
  for (int idx = tid; idx < DIM; idx += NT) {
    int i0 = idx / 196, j0 = (idx / CUT) % CUT, k0 = idx % CUT;
    spl[idx] = pk2(sd[i0]*sd[CUT + j0]*sd[2*CUT + k0], 0.0f);
  }

  // ---- BS job decode: 392 jobs = (sector cell) x (fiber half of 7) ----
  int s = 0, csz = 1, pm = 0, gbase = 0, row = 0, col = 0, r0 = 0;
  const bool bs_act = (tid < 392);
  if (bs_act) {
    int jj = tid, cum = 0, ss = 0;
    for (ss = 0; ss < 27; ss++) {
      int cc = (ss < CUT) ? ss + 1 : 27 - ss;
      if (jj < cum + 2*cc) break;
      cum += 2*cc;
    }
    s   = ss;
    csz = (s < CUT) ? s + 1 : 27 - s;
    pm  = (s < CUT) ? 0 : s - 13;
    int q = jj - cum;
    int half = q / csz;
    int idxs = q % csz;
    r0  = half * 7;
    row = pm + idxs; col = s - row;
    int off = (s < CUT) ? s*(s+1)*(2*s+1)/6 : SECT - ((27-s)*(28-s)*(55-2*s))/6;
    gbase = off + idxs*csz;
  }
  const int in01 = (pm*13 + s)*CUT;         // mode01 input base (u stride 182)
  const int ob01 = (row*CUT + col)*CUT;     // mode01 output base
  const int in12 = pm*13 + s;               // mode12 input base (u stride 13)
  const int ob12 = row*CUT + col;           // mode12 output cell (i stride 196)

  // ---- single-mode job decode: 392 jobs = (output row a) x (fiber group of 7) ----
  const int sm_a   = tid % CUT;             // output row
  const int sm_grp = tid / CUT;             // fiber group (0..27 valid)
  const bool sm_act = (tid < 392);
  __syncthreads();

  const int m1s[3] = {0, 1, 0};   // PAIRS = [(0,1),(1,2),(0,1)]
  for (int l = 0; l < 2; l++) {
    for (int half_ = 0; half_ < 2; half_++) {
      // ---- 3 beamsplitter gates ----
      for (int p = 0; p < 3; p++) {
        const float4* gm4 = (const float4*)g_bs[(circ*2 + l)*6 + half_*3 + p];
        for (int ii = tid; ii < SECT/2; ii += NT) {   // 128-bit staging loads
          float4 w2 = gm4[ii];
          sgxx[2*ii]   = pk2(w2.x, w2.x);
          sgyy[2*ii]   = pk2(w2.y, w2.y);
          sgxx[2*ii+1] = pk2(w2.z, w2.z);
          sgyy[2*ii+1] = pk2(w2.w, w2.w);
        }
        __syncthreads();
        unsigned long long accA[7], accB[7];
        if (bs_act) {
          #pragma unroll
          for (int r = 0; r < 7; r++) { accA[r] = 0ull; accB[r] = 0ull; }
          if (m1s[p] == 0) {          // contract axes (0,1); fiber axis 2 (stride 1)
            const unsigned long long* fbase = spl + in01 + r0;
            for (int u = 0; u < csz; u++) {
              unsigned long long wxx = sgxx[gbase + u], wyy = sgyy[gbase + u];
              const unsigned long long* f = fbase + u*182;
              #pragma unroll
              for (int r = 0; r < 7; r++) {
                unsigned long long v = f[r];
                accA[r] = f2fma(wxx, v, accA[r]);
                accB[r] = f2fma(wyy, v, accB[r]);
              }
            }
          } else {                    // contract axes (1,2); fiber axis 0 (stride 196)
            const unsigned long long* fbase = spl + in12 + r0*196;
            for (int u = 0; u < csz; u++) {
              unsigned long long wxx = sgxx[gbase + u], wyy = sgyy[gbase + u];
              const unsigned long long* f = fbase + u*13;
              #pragma unroll
              for (int r = 0; r < 7; r++) {
                unsigned long long v = f[r*196];
                accA[r] = f2fma(wxx, v, accA[r]);
                accB[r] = f2fma(wyy, v, accB[r]);
              }
            }
          }
        }
        __syncthreads();
        if (bs_act) {
          #pragma unroll
          for (int r = 0; r < 7; r++) {
            float ax, ay, bx, by;
            upk2(accA[r], ax, ay); upk2(accB[r], bx, by);
            unsigned long long res = pk2(ax - by, ay + bx);
            if (m1s[p] == 0) spl[ob01 + r0 + r] = res;
            else             spl[(r0 + r)*196 + ob12] = res;
          }
        }
        __syncthreads();
      }
      // ---- 3 combined single-mode gates (direct [a][t] layout, 392-thread staging) ----
      for (int m = 0; m < 3; m++) {
        const float2* gm = g_sng[(circ*2 + l)*6 + half_*3 + m];
        if (tid < 392) {
          int e = tid % 196;                 // e = a*CUT + t
          float2 w = gm[e];
          if (tid < 196) sgxx[e] = pk2(w.x, w.x);
          else           sgyy[e] = pk2(w.y, w.y);
        }
        __syncthreads();
        unsigned long long accA[7], accB[7];
        int start = 0, ts = 1, fs = 1;
        if (sm_act) {
          if (m == 0)      { start = sm_grp*7;                                ts = 196; fs = 1;  }
          else if (m == 1) { start = (sm_grp >> 1)*196 + (sm_grp & 1)*7;      ts = CUT; fs = 1;  }
          else             { start = sm_grp*7*CUT;                            ts = 1;   fs = CUT;}
          #pragma unroll
          for (int q = 0; q < 7; q++) { accA[q] = 0ull; accB[q] = 0ull; }
          for (int t = 0; t < CUT; t++) {
            unsigned long long gxx = sgxx[sm_a*CUT + t], gyy = sgyy[sm_a*CUT + t];
            const unsigned long long* f = spl + start + t*ts;
            #pragma unroll
            for (int q = 0; q < 7; q++) {
              unsigned long long v = f[q*fs];
              accA[q] = f2fma(gxx, v, accA[q]);
              accB[q] = f2fma(gyy, v, accB[q]);
            }
          }
        }
        __syncthreads();
        if (sm_act) {
          unsigned long long* o = spl + start + sm_a*ts;
          #pragma unroll
          for (int q = 0; q < 7; q++) {
            float ax, ay, bx, by;
            upk2(accA[q], ax, ay); upk2(accB[q], bx, by);
            o[q*fs] = pk2(ax - by, ay + bx);
          }
        }
        __syncthreads();
      }
    }
  }

  // ---- expectations: single fused sweep for all 3 modes ----
  {
    float l0 = 0.f, l1 = 0.f, l2 = 0.f;
    for (int idx = tid; idx < DIM; idx += NT) {
      int i0 = idx / 196, rem = idx % 196;
      int j0 = rem / CUT, k0 = rem % CUT;
      float2 a2 = sp[idx];
      if (i0 < CUT-1) {
        float2 b2 = sp[idx + 196];
        l0 += sqrtf((float)(i0+1)) * (a2.x*b2.x + a2.y*b2.y);
      }
      if (j0 < CUT-1) {
        float2 b2 = sp[idx + CUT];
        l1 += sqrtf((float)(j0+1)) * (a2.x*b2.x + a2.y*b2.y);
      }
      if (k0 < CUT-1) {
        float2 b2 = sp[idx + 1];
        l2 += sqrtf((float)(k0+1)) * (a2.x*b2.x + a2.y*b2.y);
      }
    }
    #pragma unroll
    for (int o = 16; o > 0; o >>= 1) {
      l0 += __shfl_down_sync(0xffffffffu, l0, o);
      l1 += __shfl_down_sync(0xffffffffu, l1, o);
      l2 += __shfl_down_sync(0xffffffffu, l2, o);
    }
    if ((tid & 31) == 0) {
      sred[0][tid >> 5] = l0;
      sred[1][tid >> 5] = l1;
      sred[2][tid >> 5] = l2;
    }
    __syncthreads();
    if (tid < 3) {
      float tot = 0.f;
      #pragma unroll
      for (int w2 = 0; w2 < NT/32; w2++) tot += sred[tid][w2];
      out[b*6 + circ*3 + tid] = 2.f * tot;
    }
  }
}

// ================================ launch ================================
extern "C" void kernel_launch(void* const* d_in, const int* in_sizes, int n_in,
                              void* d_out, int out_size)
{
  (void)in_sizes; (void)n_in; (void)out_size;
  const float* x    = (const float*)d_in[0];
  const float* th1  = (const float*)d_in[1];
  const float* ph1  = (const float*)d_in[2];
  const float* vph1 = (const float*)d_in[3];
  const float* rr   = (const float*)d_in[4];
  const float* phr  = (const float*)d_in[5];
  const float* th2  = (const float*)d_in[6];
  const float* ph2  = (const float*)d_in[7];
  const float* vph2 = (const float*)d_in[8];
  const float* aa   = (const float*)d_in[9];
  const float* pha  = (const float*)d_in[10];
  const float* kk   = (const float*)d_in[11];

  gates_kernel<<<672, 196>>>(th1, ph1, vph1, rr, phr, th2, ph2, vph2, aa, pha, kk);
  dvec_kernel<<<24, 256>>>(x);
  dim3 grid(1024, 2);
  evolve_kernel<<<grid, NT>>>((float*)d_out);
}